// round 6
// baseline (speedup 1.0000x reference)
#include <cuda_runtime.h>
#include <cuda_fp16.h>
#include <math.h>

#define HIDDEN 64
#define MBATCH 32
#define ATOM   64
#define NUM_RBF 300

#define S_INT   512
#define TAB_ROWS 513                    // row s = h(s*H_STEP), s in [0,512]
#define H_STEP  (10.0f / 512.0f)
#define INV_H   51.2f

typedef unsigned long long u64;

// device scratch (no allocations allowed)
__device__ __align__(16) unsigned g_table_h[515 * 32];   // fp16x2 table, row=128B
__device__ __align__(16) float g_v1[MBATCH * ATOM * HIDDEN];
__device__ __align__(16) float g_W2t[HIDDEN * HIDDEN];
__device__ __align__(16) float g_W3t[HIDDEN * HIDDEN];

__device__ __forceinline__ float softplus_f(float v) {
    return fmaxf(v, 0.0f) + log1pf(expf(-fabsf(v)));
}

// packed f32x2 helpers (Blackwell FFMA2 / FADD2)
__device__ __forceinline__ u64 fma2(u64 a, u64 b, u64 c) {
    u64 d; asm("fma.rn.f32x2 %0, %1, %2, %3;" : "=l"(d) : "l"(a), "l"(b), "l"(c)); return d;
}
__device__ __forceinline__ u64 add2(u64 a, u64 b) {
    u64 d; asm("add.rn.f32x2 %0, %1, %2;" : "=l"(d) : "l"(a), "l"(b)); return d;
}
__device__ __forceinline__ u64 pack2(float a, float b) {
    u64 d; asm("mov.b64 %0, {%1, %2};" : "=l"(d) : "f"(a), "f"(b)); return d;
}
__device__ __forceinline__ float2 unpk2(u64 v) {
    float2 f; asm("mov.b64 {%0, %1}, %2;" : "=f"(f.x), "=f"(f.y) : "l"(v)); return f;
}
__device__ __forceinline__ u64 dup2(float v) {
    u64 d; asm("mov.b64 %0, {%1, %1};" : "=l"(d) : "f"(v)); return d;
}
__device__ __forceinline__ unsigned h2bits(float w) {
    __half2 h = __float2half2_rn(w);
    return *reinterpret_cast<unsigned*>(&h);
}
__device__ __forceinline__ __half2 bits2h(unsigned u) {
    return *reinterpret_cast<__half2*>(&u);
}

// ---------------------------------------------------------------------------
// Prep kernel (unchanged), 512 threads/block
// ---------------------------------------------------------------------------
#define TAB_BLOCKS 65
#define V1_BLOCKS  64
#define PREP_BLOCKS (TAB_BLOCKS + V1_BLOCKS + 1)
#define PREP_SMEM ((64*301 + 64*65 + 8*304 + 8*64) * 4)

__global__ void __launch_bounds__(512) prep_kernel(
    const float* __restrict__ x,  const float* __restrict__ W1, const float* __restrict__ b1,
    const float* __restrict__ W2, const float* __restrict__ W3,
    const float* __restrict__ Wd1, const float* __restrict__ bd1,
    const float* __restrict__ Wd2, const float* __restrict__ bd2)
{
    extern __shared__ float sh[];
    const int tid = threadIdx.x;
    const int b = blockIdx.x;

    if (b < TAB_BLOCKS) {
        float* Wd1_s = sh;                   // 64 x 301 (padded)
        float* Wd2_s = Wd1_s + 64 * 301;     // 64 x 65
        float* rbf_s = Wd2_s + 64 * 65;      // 8 x 304
        float* g_s   = rbf_s + 8 * 304;      // 8 x 64

        for (int idx = tid; idx < 64 * NUM_RBF; idx += 512) {
            int cc = idx / NUM_RBF;
            int r  = idx - cc * NUM_RBF;
            Wd1_s[cc * 301 + r] = Wd1[idx];
        }
        for (int idx = tid; idx < 4096; idx += 512)
            Wd2_s[(idx >> 6) * 65 + (idx & 63)] = Wd2[idx];
        const int s0 = b * 8;
        for (int idx = tid; idx < 8 * NUM_RBF; idx += 512) {
            int qq = idx / NUM_RBF;
            int r  = idx - qq * NUM_RBF;
            float dd = (float)(s0 + qq) * H_STEP;
            float u = dd - 0.1f * (float)r;
            rbf_s[qq * 304 + r] = __expf(-10.0f * u * u);
        }
        __syncthreads();

        const int q = tid >> 6;
        const int c = tid & 63;
        const int s = s0 + q;
        const float d = (float)s * H_STEP;
        int rlo = (int)ceilf((d - 1.5f) * 10.0f); if (rlo < 0) rlo = 0;
        int rhi = (int)floorf((d + 1.5f) * 10.0f); if (rhi > NUM_RBF - 1) rhi = NUM_RBF - 1;
        float p = bd1[c];
        const float* wrow = Wd1_s + c * 301;
        const float* rrow = rbf_s + q * 304;
        for (int r = rlo; r <= rhi; r++) p = fmaf(wrow[r], rrow[r], p);
        g_s[q * 64 + c] = softplus_f(p);
        __syncthreads();

        float qv = bd2[c];
        const float* w2row = Wd2_s + c * 65;
        const float* gg = g_s + q * 64;
        #pragma unroll 8
        for (int k = 0; k < 64; k++) qv = fmaf(w2row[k], gg[k], qv);
        if (s < TAB_ROWS)
            ((__half*)g_table_h)[s * 64 + c] = __float2half_rn(softplus_f(qv));
    } else if (b < TAB_BLOCKS + V1_BLOCKS) {
        const int v = b - TAB_BLOCKS;
        const int m = v >> 1, half = v & 1;
        float* W1p = sh;                 // 64 x 68 padded
        float* xp  = sh + 64 * 68;       // 32 x 68

        for (int idx = tid; idx < 4096; idx += 512)
            W1p[(idx >> 6) * 68 + (idx & 63)] = W1[idx];
        for (int idx = tid; idx < 2048; idx += 512)
            xp[(idx >> 6) * 68 + (idx & 63)] = x[m * 4096 + (half * 32 + (idx >> 6)) * 64 + (idx & 63)];
        __syncthreads();

        const int ii = tid & 31;
        const int oh = tid >> 5;
        float4 acc = make_float4(0.f, 0.f, 0.f, 0.f);
        const float* xr = xp + ii * 68;
        const float* wr = W1p + oh * 4 * 68;
        #pragma unroll
        for (int c4 = 0; c4 < 16; c4++) {
            float4 xv = *(const float4*)(xr + c4 * 4);
            float4 w0 = *(const float4*)(wr + 0 * 68 + c4 * 4);
            float4 w1 = *(const float4*)(wr + 1 * 68 + c4 * 4);
            float4 w2 = *(const float4*)(wr + 2 * 68 + c4 * 4);
            float4 w3 = *(const float4*)(wr + 3 * 68 + c4 * 4);
            acc.x = fmaf(xv.x, w0.x, fmaf(xv.y, w0.y, fmaf(xv.z, w0.z, fmaf(xv.w, w0.w, acc.x))));
            acc.y = fmaf(xv.x, w1.x, fmaf(xv.y, w1.y, fmaf(xv.z, w1.z, fmaf(xv.w, w1.w, acc.y))));
            acc.z = fmaf(xv.x, w2.x, fmaf(xv.y, w2.y, fmaf(xv.z, w2.z, fmaf(xv.w, w2.w, acc.z))));
            acc.w = fmaf(xv.x, w3.x, fmaf(xv.y, w3.y, fmaf(xv.z, w3.z, fmaf(xv.w, w3.w, acc.w))));
        }
        float4 bv = *(const float4*)(b1 + oh * 4);
        acc.x += bv.x; acc.y += bv.y; acc.z += bv.z; acc.w += bv.w;
        *(float4*)(g_v1 + (m * 64 + half * 32 + ii) * 64 + oh * 4) = acc;
    } else {
        for (int idx = tid; idx < 8192; idx += 512) {
            const float* src = (idx < 4096) ? W2 : W3;
            float* dst = (idx < 4096) ? g_W2t : g_W3t;
            int e = idx & 4095;
            dst[e] = src[(e & 63) * 64 + (e >> 6)];
        }
    }
}

// ---------------------------------------------------------------------------
// Main kernel: 256 blocks = (m, j-group of 8), 512 threads (16 warps),
// 2 CTAs per SM (99.2 KB smem each). Warp = (ihalf, jj); lane = channel
// pair. Quadratic 3-tap fp16 interpolation, conflict-free layout.
// ---------------------------------------------------------------------------
// smem floats: TAB 16480 | V1 4096 | W4 2048 | PART 1024 | PAIR 512 |
// V2 512 | B2 64 | B3 64 = 24800 floats = 99200 B -> 2 CTAs/SM
#define MAIN_SMEM (24800 * 4)

__global__ void __launch_bounds__(512) main_kernel(
    const float* __restrict__ x, const float* __restrict__ dist,
    const float* __restrict__ b2, const float* __restrict__ b3,
    float* __restrict__ out)
{
    extern __shared__ float sh[];
    unsigned* TABu = (unsigned*)sh;       // fp16 table; reused as W2T/W3T later
    float* V1s  = sh + 16480;             // 4096
    float* W4s  = V1s + 4096;             // 2048 : per-pair (wm,w0,wp h2-bits, koff)
    float* PARTs= W4s + 2048;             // 1024 : 2-way u64 partials
    float* PAIRs= PARTs + 1024;           // 512
    float* V2s  = PAIRs + 512;            // 512
    float* B2s  = V2s + 512;              // 64
    float* B3s  = B2s + 64;               // 64

    const int tid = threadIdx.x;
    const int m  = blockIdx.x >> 3;
    const int j0 = (blockIdx.x & 7) << 3;

    // stage table (fp16, 64.4KB) + v1 + biases
    {
        const uint4* ts = (const uint4*)g_table_h;
        uint4* td = (uint4*)TABu;
        #pragma unroll
        for (int r = 0; r < 8; r++) td[tid + r * 512] = ts[tid + r * 512];
        if (tid < 24) td[4096 + tid] = ts[4096 + tid];
        const float4* vs = (const float4*)(g_v1 + m * 4096);
        float4* vd = (float4*)V1s;
        vd[tid] = vs[tid];
        vd[tid + 512] = vs[tid + 512];
        if (tid < 64) B2s[tid] = b2[tid];
        else if (tid < 128) B3s[tid - 64] = b3[tid - 64];
    }
    // per-pair quadratic weights around nearest node k (nodes k-1,k,k+1)
    {
        const int p = tid;                 // 512 pairs: (i, jj)
        const int i = p >> 3, jj = p & 7;
        float d = dist[(m * 64 + i) * 64 + j0 + jj];
        float t = d * INV_H;
        int k = __float2int_rn(t);
        k = min(max(k, 1), S_INT - 1);
        float u = t - (float)k;
        float wm = 0.5f * u * (u - 1.0f);
        float w0 = 1.0f - u * u;
        float wp = 0.5f * u * (u + 1.0f);
        float4 wk;
        wk.x = __uint_as_float(h2bits(wm));
        wk.y = __uint_as_float(h2bits(w0));
        wk.z = __uint_as_float(h2bits(wp));
        wk.w = __int_as_float((k - 1) << 7);   // byte offset of first tap row
        ((float4*)W4s)[p] = wk;
    }
    __syncthreads();

    const int warp  = tid >> 5;
    const int jj    = warp & 7;      // destination atom within group
    const int ihalf = warp >> 3;     // 0..1 : i-range half
    const int t     = tid & 31;      // lane = channel pair (2t, 2t+1)

    u64 acc = 0ull;
    const char* tb = (const char*)TABu + (t << 2);
    const u64* V1v = (const u64*)V1s;
    const float4* W4v = ((const float4*)W4s) + jj;
    const int ibase = ihalf << 5;

    #pragma unroll 4
    for (int ii = 0; ii < 32; ii++) {
        const int i = ibase + ii;
        float4 wk = W4v[i << 3];                     // broadcast
        int koff = __float_as_int(wk.w);
        unsigned r0 = *(const unsigned*)(tb + koff);
        unsigned r1 = *(const unsigned*)(tb + koff + 128);
        unsigned r2 = *(const unsigned*)(tb + koff + 256);
        __half2 h2 = __hfma2(bits2h(__float_as_uint(wk.x)), bits2h(r0),
                     __hfma2(bits2h(__float_as_uint(wk.y)), bits2h(r1),
                     __hmul2(bits2h(__float_as_uint(wk.z)), bits2h(r2))));
        float2 hf = __half22float2(h2);
        u64 vv = V1v[(i << 5) + t];
        acc = fma2(vv, pack2(hf.x, hf.y), acc);
    }
    ((u64*)PARTs)[(ihalf << 8) + (jj << 5) + t] = acc;
    __syncthreads();

    // reduce 2-way partials; stage W2T/W3T into dead table region
    if (tid < 256) {
        u64 a = add2(((const u64*)PARTs)[tid], ((const u64*)PARTs)[tid + 256]);
        ((u64*)PAIRs)[tid] = a;
    }
    float* W2Ts = (float*)TABu;
    float* W3Ts = W2Ts + 4096;
    {
        const float4* w2s = (const float4*)g_W2t;
        const float4* w3s = (const float4*)g_W3t;
        ((float4*)W2Ts)[tid]       = w2s[tid];
        ((float4*)W2Ts)[tid + 512] = w2s[tid + 512];
        ((float4*)W3Ts)[tid]       = w3s[tid];
        ((float4*)W3Ts)[tid + 512] = w3s[tid + 512];
    }
    __syncthreads();

    // epilogue: 8 warps, each handles one j-row; lane = output pair (2t,2t+1)
    if (tid < 256) {
        const int g = tid >> 5;      // j-row 0..7

        // layer 2: v2 = softplus(PAIR @ W2^T + b2)
        u64 a0;
        {
            a0 = ((const u64*)B2s)[t];
            const float4* pr0 = (const float4*)(PAIRs + g * 64);
            const u64* wv = (const u64*)W2Ts;
            #pragma unroll 4
            for (int c4 = 0; c4 < 16; c4++) {
                float4 p0 = pr0[c4];
                u64 w0 = wv[(c4 * 4 + 0) * 32 + t];
                u64 w1 = wv[(c4 * 4 + 1) * 32 + t];
                u64 w2 = wv[(c4 * 4 + 2) * 32 + t];
                u64 w3 = wv[(c4 * 4 + 3) * 32 + t];
                a0 = fma2(dup2(p0.x), w0, a0);
                a0 = fma2(dup2(p0.y), w1, a0);
                a0 = fma2(dup2(p0.z), w2, a0);
                a0 = fma2(dup2(p0.w), w3, a0);
            }
            float2 f0 = unpk2(a0);
            ((u64*)V2s)[g * 32 + t] = pack2(softplus_f(f0.x), softplus_f(f0.y));
        }
        __syncwarp();

        // layer 3 + residual
        {
            a0 = ((const u64*)B3s)[t];
            const float4* pr0 = (const float4*)(V2s + g * 64);
            const u64* wv = (const u64*)W3Ts;
            #pragma unroll 4
            for (int c4 = 0; c4 < 16; c4++) {
                float4 p0 = pr0[c4];
                u64 w0 = wv[(c4 * 4 + 0) * 32 + t];
                u64 w1 = wv[(c4 * 4 + 1) * 32 + t];
                u64 w2 = wv[(c4 * 4 + 2) * 32 + t];
                u64 w3 = wv[(c4 * 4 + 3) * 32 + t];
                a0 = fma2(dup2(p0.x), w0, a0);
                a0 = fma2(dup2(p0.y), w1, a0);
                a0 = fma2(dup2(p0.z), w2, a0);
                a0 = fma2(dup2(p0.w), w3, a0);
            }
            const u64* xv = (const u64*)x;
            u64* ov = (u64*)out;
            int g0 = (m * 64 + j0 + g) * 32 + t;
            float2 f0 = unpk2(a0), x0 = unpk2(xv[g0]);
            ov[g0] = pack2(f0.x + x0.x, f0.y + x0.y);
        }
    }
}

extern "C" void kernel_launch(void* const* d_in, const int* in_sizes, int n_in,
                              void* d_out, int out_size) {
    const float* x   = (const float*)d_in[0];
    const float* dist= (const float*)d_in[1];
    const float* W1  = (const float*)d_in[2];
    const float* b1  = (const float*)d_in[3];
    const float* W2  = (const float*)d_in[4];
    const float* b2  = (const float*)d_in[5];
    const float* W3  = (const float*)d_in[6];
    const float* b3  = (const float*)d_in[7];
    const float* Wd1 = (const float*)d_in[8];
    const float* bd1 = (const float*)d_in[9];
    const float* Wd2 = (const float*)d_in[10];
    const float* bd2 = (const float*)d_in[11];
    float* out = (float*)d_out;
    (void)in_sizes; (void)n_in; (void)out_size;

    cudaFuncSetAttribute(prep_kernel, cudaFuncAttributeMaxDynamicSharedMemorySize, PREP_SMEM);
    cudaFuncSetAttribute(main_kernel, cudaFuncAttributeMaxDynamicSharedMemorySize, MAIN_SMEM);

    prep_kernel<<<PREP_BLOCKS, 512, PREP_SMEM>>>(x, W1, b1, W2, W3, Wd1, bd1, Wd2, bd2);
    main_kernel<<<256, 512, MAIN_SMEM>>>(x, dist, b2, b3, out);
}

// round 7
// speedup vs baseline: 1.0107x; 1.0107x over previous
#include <cuda_runtime.h>
#include <cuda_fp16.h>
#include <math.h>

#define HIDDEN 64
#define MBATCH 32
#define ATOM   64
#define NUM_RBF 300

#define S_INT   512
#define TAB_ROWS 513                    // row s = h(s*H_STEP), s in [0,512]
#define H_STEP  (10.0f / 512.0f)
#define INV_H   51.2f

typedef unsigned long long u64;

// device scratch (no allocations allowed)
__device__ __align__(16) unsigned g_table_h[515 * 32];   // fp16x2 table, row=128B
__device__ __align__(16) float g_v1[MBATCH * ATOM * HIDDEN];
__device__ __align__(16) float g_W2t[HIDDEN * HIDDEN];
__device__ __align__(16) float g_W3t[HIDDEN * HIDDEN];

__device__ __forceinline__ float softplus_f(float v) {
    return fmaxf(v, 0.0f) + log1pf(expf(-fabsf(v)));
}

// packed f32x2 helpers (Blackwell FFMA2 / FADD2)
__device__ __forceinline__ u64 fma2(u64 a, u64 b, u64 c) {
    u64 d; asm("fma.rn.f32x2 %0, %1, %2, %3;" : "=l"(d) : "l"(a), "l"(b), "l"(c)); return d;
}
__device__ __forceinline__ u64 add2(u64 a, u64 b) {
    u64 d; asm("add.rn.f32x2 %0, %1, %2;" : "=l"(d) : "l"(a), "l"(b)); return d;
}
__device__ __forceinline__ u64 pack2(float a, float b) {
    u64 d; asm("mov.b64 %0, {%1, %2};" : "=l"(d) : "f"(a), "f"(b)); return d;
}
__device__ __forceinline__ float2 unpk2(u64 v) {
    float2 f; asm("mov.b64 {%0, %1}, %2;" : "=f"(f.x), "=f"(f.y) : "l"(v)); return f;
}
__device__ __forceinline__ u64 dup2(float v) {
    u64 d; asm("mov.b64 %0, {%1, %1};" : "=l"(d) : "f"(v)); return d;
}
__device__ __forceinline__ unsigned h2bits(float w) {
    __half2 h = __float2half2_rn(w);
    return *reinterpret_cast<unsigned*>(&h);
}
__device__ __forceinline__ __half2 bits2h(unsigned u) {
    return *reinterpret_cast<__half2*>(&u);
}

// ---------------------------------------------------------------------------
// Prep kernel (unchanged), 512 threads/block
// ---------------------------------------------------------------------------
#define TAB_BLOCKS 65
#define V1_BLOCKS  64
#define PREP_BLOCKS (TAB_BLOCKS + V1_BLOCKS + 1)
#define PREP_SMEM ((64*301 + 64*65 + 8*304 + 8*64) * 4)

__global__ void __launch_bounds__(512) prep_kernel(
    const float* __restrict__ x,  const float* __restrict__ W1, const float* __restrict__ b1,
    const float* __restrict__ W2, const float* __restrict__ W3,
    const float* __restrict__ Wd1, const float* __restrict__ bd1,
    const float* __restrict__ Wd2, const float* __restrict__ bd2)
{
    extern __shared__ float sh[];
    const int tid = threadIdx.x;
    const int b = blockIdx.x;

    if (b < TAB_BLOCKS) {
        float* Wd1_s = sh;                   // 64 x 301 (padded)
        float* Wd2_s = Wd1_s + 64 * 301;     // 64 x 65
        float* rbf_s = Wd2_s + 64 * 65;      // 8 x 304
        float* g_s   = rbf_s + 8 * 304;      // 8 x 64

        for (int idx = tid; idx < 64 * NUM_RBF; idx += 512) {
            int cc = idx / NUM_RBF;
            int r  = idx - cc * NUM_RBF;
            Wd1_s[cc * 301 + r] = Wd1[idx];
        }
        for (int idx = tid; idx < 4096; idx += 512)
            Wd2_s[(idx >> 6) * 65 + (idx & 63)] = Wd2[idx];
        const int s0 = b * 8;
        for (int idx = tid; idx < 8 * NUM_RBF; idx += 512) {
            int qq = idx / NUM_RBF;
            int r  = idx - qq * NUM_RBF;
            float dd = (float)(s0 + qq) * H_STEP;
            float u = dd - 0.1f * (float)r;
            rbf_s[qq * 304 + r] = __expf(-10.0f * u * u);
        }
        __syncthreads();

        const int q = tid >> 6;
        const int c = tid & 63;
        const int s = s0 + q;
        const float d = (float)s * H_STEP;
        int rlo = (int)ceilf((d - 1.5f) * 10.0f); if (rlo < 0) rlo = 0;
        int rhi = (int)floorf((d + 1.5f) * 10.0f); if (rhi > NUM_RBF - 1) rhi = NUM_RBF - 1;
        float p = bd1[c];
        const float* wrow = Wd1_s + c * 301;
        const float* rrow = rbf_s + q * 304;
        for (int r = rlo; r <= rhi; r++) p = fmaf(wrow[r], rrow[r], p);
        g_s[q * 64 + c] = softplus_f(p);
        __syncthreads();

        float qv = bd2[c];
        const float* w2row = Wd2_s + c * 65;
        const float* gg = g_s + q * 64;
        #pragma unroll 8
        for (int k = 0; k < 64; k++) qv = fmaf(w2row[k], gg[k], qv);
        if (s < TAB_ROWS)
            ((__half*)g_table_h)[s * 64 + c] = __float2half_rn(softplus_f(qv));
    } else if (b < TAB_BLOCKS + V1_BLOCKS) {
        const int v = b - TAB_BLOCKS;
        const int m = v >> 1, half = v & 1;
        float* W1p = sh;                 // 64 x 68 padded
        float* xp  = sh + 64 * 68;       // 32 x 68

        for (int idx = tid; idx < 4096; idx += 512)
            W1p[(idx >> 6) * 68 + (idx & 63)] = W1[idx];
        for (int idx = tid; idx < 2048; idx += 512)
            xp[(idx >> 6) * 68 + (idx & 63)] = x[m * 4096 + (half * 32 + (idx >> 6)) * 64 + (idx & 63)];
        __syncthreads();

        const int ii = tid & 31;
        const int oh = tid >> 5;
        float4 acc = make_float4(0.f, 0.f, 0.f, 0.f);
        const float* xr = xp + ii * 68;
        const float* wr = W1p + oh * 4 * 68;
        #pragma unroll
        for (int c4 = 0; c4 < 16; c4++) {
            float4 xv = *(const float4*)(xr + c4 * 4);
            float4 w0 = *(const float4*)(wr + 0 * 68 + c4 * 4);
            float4 w1 = *(const float4*)(wr + 1 * 68 + c4 * 4);
            float4 w2 = *(const float4*)(wr + 2 * 68 + c4 * 4);
            float4 w3 = *(const float4*)(wr + 3 * 68 + c4 * 4);
            acc.x = fmaf(xv.x, w0.x, fmaf(xv.y, w0.y, fmaf(xv.z, w0.z, fmaf(xv.w, w0.w, acc.x))));
            acc.y = fmaf(xv.x, w1.x, fmaf(xv.y, w1.y, fmaf(xv.z, w1.z, fmaf(xv.w, w1.w, acc.y))));
            acc.z = fmaf(xv.x, w2.x, fmaf(xv.y, w2.y, fmaf(xv.z, w2.z, fmaf(xv.w, w2.w, acc.z))));
            acc.w = fmaf(xv.x, w3.x, fmaf(xv.y, w3.y, fmaf(xv.z, w3.z, fmaf(xv.w, w3.w, acc.w))));
        }
        float4 bv = *(const float4*)(b1 + oh * 4);
        acc.x += bv.x; acc.y += bv.y; acc.z += bv.z; acc.w += bv.w;
        *(float4*)(g_v1 + (m * 64 + half * 32 + ii) * 64 + oh * 4) = acc;
    } else {
        for (int idx = tid; idx < 8192; idx += 512) {
            const float* src = (idx < 4096) ? W2 : W3;
            float* dst = (idx < 4096) ? g_W2t : g_W3t;
            int e = idx & 4095;
            dst[e] = src[(e & 63) * 64 + (e >> 6)];
        }
    }
}

// ---------------------------------------------------------------------------
// Main kernel: 256 blocks = (m, j-group of 8), 1024 threads (32 warps),
// 2 CTAs/SM => 64 warps/SM (full warp occupancy). Warp = (iquarter, jj);
// lane = channel pair; 16 loop iters/warp; 4-way partial reduce.
// ---------------------------------------------------------------------------
// smem floats: TAB 16480 | V1 4096 | W4 2048 | PART 2048 | PAIR 512 |
// V2 512 | B2 64 | B3 64 = 25824 floats = 103296 B -> 2 CTAs/SM
#define MAIN_SMEM (25824 * 4)

__global__ void __launch_bounds__(1024, 2) main_kernel(
    const float* __restrict__ x, const float* __restrict__ dist,
    const float* __restrict__ b2, const float* __restrict__ b3,
    float* __restrict__ out)
{
    extern __shared__ float sh[];
    unsigned* TABu = (unsigned*)sh;       // fp16 table; reused as W2T/W3T later
    float* V1s  = sh + 16480;             // 4096
    float* W4s  = V1s + 4096;             // 2048 : per-pair (wm,w0,wp h2-bits, koff)
    float* PARTs= W4s + 2048;             // 2048 : 4-way u64 partials
    float* PAIRs= PARTs + 2048;           // 512
    float* V2s  = PAIRs + 512;            // 512
    float* B2s  = V2s + 512;              // 64
    float* B3s  = B2s + 64;               // 64

    const int tid = threadIdx.x;
    const int m  = blockIdx.x >> 3;
    const int j0 = (blockIdx.x & 7) << 3;

    // stage table (fp16, 64.4KB) + v1 + biases
    {
        const uint4* ts = (const uint4*)g_table_h;
        uint4* td = (uint4*)TABu;
        #pragma unroll
        for (int r = 0; r < 4; r++) td[tid + r * 1024] = ts[tid + r * 1024];
        if (tid < 24) td[4096 + tid] = ts[4096 + tid];
        ((float4*)V1s)[tid] = ((const float4*)(g_v1 + m * 4096))[tid];
        if (tid < 64) B2s[tid] = b2[tid];
        else if (tid < 128) B3s[tid - 64] = b3[tid - 64];
    }
    // per-pair quadratic weights around nearest node k (nodes k-1,k,k+1)
    if (tid < 512) {
        const int p = tid;                 // 512 pairs: (i, jj)
        const int i = p >> 3, jj = p & 7;
        float d = dist[(m * 64 + i) * 64 + j0 + jj];
        float t = d * INV_H;
        int k = __float2int_rn(t);
        k = min(max(k, 1), S_INT - 1);
        float u = t - (float)k;
        float wm = 0.5f * u * (u - 1.0f);
        float w0 = 1.0f - u * u;
        float wp = 0.5f * u * (u + 1.0f);
        float4 wk;
        wk.x = __uint_as_float(h2bits(wm));
        wk.y = __uint_as_float(h2bits(w0));
        wk.z = __uint_as_float(h2bits(wp));
        wk.w = __int_as_float((k - 1) << 7);   // byte offset of first tap row
        ((float4*)W4s)[p] = wk;
    }
    __syncthreads();

    const int warp  = tid >> 5;
    const int jj    = warp & 7;      // destination atom within group
    const int iq    = warp >> 3;     // 0..3 : i-range quarter
    const int t     = tid & 31;      // lane = channel pair (2t, 2t+1)

    u64 acc = 0ull;
    const char* tb = (const char*)TABu + (t << 2);
    const u64* V1v = (const u64*)V1s;
    const float4* W4v = ((const float4*)W4s) + jj;
    const int ibase = iq << 4;

    #pragma unroll 4
    for (int ii = 0; ii < 16; ii++) {
        const int i = ibase + ii;
        float4 wk = W4v[i << 3];                     // broadcast
        int koff = __float_as_int(wk.w);
        unsigned r0 = *(const unsigned*)(tb + koff);
        unsigned r1 = *(const unsigned*)(tb + koff + 128);
        unsigned r2 = *(const unsigned*)(tb + koff + 256);
        __half2 h2 = __hfma2(bits2h(__float_as_uint(wk.x)), bits2h(r0),
                     __hfma2(bits2h(__float_as_uint(wk.y)), bits2h(r1),
                     __hmul2(bits2h(__float_as_uint(wk.z)), bits2h(r2))));
        float2 hf = __half22float2(h2);
        u64 vv = V1v[(i << 5) + t];
        acc = fma2(vv, pack2(hf.x, hf.y), acc);
    }
    ((u64*)PARTs)[(iq << 8) + (jj << 5) + t] = acc;
    __syncthreads();

    // reduce 4-way partials; stage W2T/W3T into dead table region
    if (tid < 256) {
        const u64* pp = (const u64*)PARTs;
        u64 a = add2(add2(pp[tid], pp[tid + 256]),
                     add2(pp[tid + 512], pp[tid + 768]));
        ((u64*)PAIRs)[tid] = a;
    }
    float* W2Ts = (float*)TABu;
    float* W3Ts = W2Ts + 4096;
    {
        ((float4*)W2Ts)[tid] = ((const float4*)g_W2t)[tid];
        ((float4*)W3Ts)[tid] = ((const float4*)g_W3t)[tid];
    }
    __syncthreads();

    // epilogue: 8 warps, each handles one j-row; lane = output pair (2t,2t+1)
    if (tid < 256) {
        const int g = tid >> 5;      // j-row 0..7

        // layer 2: v2 = softplus(PAIR @ W2^T + b2)
        u64 a0;
        {
            a0 = ((const u64*)B2s)[t];
            const float4* pr0 = (const float4*)(PAIRs + g * 64);
            const u64* wv = (const u64*)W2Ts;
            #pragma unroll 4
            for (int c4 = 0; c4 < 16; c4++) {
                float4 p0 = pr0[c4];
                u64 w0 = wv[(c4 * 4 + 0) * 32 + t];
                u64 w1 = wv[(c4 * 4 + 1) * 32 + t];
                u64 w2 = wv[(c4 * 4 + 2) * 32 + t];
                u64 w3 = wv[(c4 * 4 + 3) * 32 + t];
                a0 = fma2(dup2(p0.x), w0, a0);
                a0 = fma2(dup2(p0.y), w1, a0);
                a0 = fma2(dup2(p0.z), w2, a0);
                a0 = fma2(dup2(p0.w), w3, a0);
            }
            float2 f0 = unpk2(a0);
            ((u64*)V2s)[g * 32 + t] = pack2(softplus_f(f0.x), softplus_f(f0.y));
        }
        __syncwarp();

        // layer 3 + residual
        {
            a0 = ((const u64*)B3s)[t];
            const float4* pr0 = (const float4*)(V2s + g * 64);
            const u64* wv = (const u64*)W3Ts;
            #pragma unroll 4
            for (int c4 = 0; c4 < 16; c4++) {
                float4 p0 = pr0[c4];
                u64 w0 = wv[(c4 * 4 + 0) * 32 + t];
                u64 w1 = wv[(c4 * 4 + 1) * 32 + t];
                u64 w2 = wv[(c4 * 4 + 2) * 32 + t];
                u64 w3 = wv[(c4 * 4 + 3) * 32 + t];
                a0 = fma2(dup2(p0.x), w0, a0);
                a0 = fma2(dup2(p0.y), w1, a0);
                a0 = fma2(dup2(p0.z), w2, a0);
                a0 = fma2(dup2(p0.w), w3, a0);
            }
            const u64* xv = (const u64*)x;
            u64* ov = (u64*)out;
            int g0 = (m * 64 + j0 + g) * 32 + t;
            float2 f0 = unpk2(a0), x0 = unpk2(xv[g0]);
            ov[g0] = pack2(f0.x + x0.x, f0.y + x0.y);
        }
    }
}

extern "C" void kernel_launch(void* const* d_in, const int* in_sizes, int n_in,
                              void* d_out, int out_size) {
    const float* x   = (const float*)d_in[0];
    const float* dist= (const float*)d_in[1];
    const float* W1  = (const float*)d_in[2];
    const float* b1  = (const float*)d_in[3];
    const float* W2  = (const float*)d_in[4];
    const float* b2  = (const float*)d_in[5];
    const float* W3  = (const float*)d_in[6];
    const float* b3  = (const float*)d_in[7];
    const float* Wd1 = (const float*)d_in[8];
    const float* bd1 = (const float*)d_in[9];
    const float* Wd2 = (const float*)d_in[10];
    const float* bd2 = (const float*)d_in[11];
    float* out = (float*)d_out;
    (void)in_sizes; (void)n_in; (void)out_size;

    cudaFuncSetAttribute(prep_kernel, cudaFuncAttributeMaxDynamicSharedMemorySize, PREP_SMEM);
    cudaFuncSetAttribute(main_kernel, cudaFuncAttributeMaxDynamicSharedMemorySize, MAIN_SMEM);

    prep_kernel<<<PREP_BLOCKS, 512, PREP_SMEM>>>(x, W1, b1, W2, W3, Wd1, bd1, Wd2, bd2);
    main_kernel<<<256, 1024, MAIN_SMEM>>>(x, dist, b2, b3, out);
}